// round 14
// baseline (speedup 1.0000x reference)
#include <cuda_runtime.h>
#include <mma.h>
#include <cstdint>
#include <cstddef>

using namespace nvcuda;

// Problem constants (fixed by setup_inputs)
#define NMAX 50000
#define KMAX 768
#define CMAX 512
#define EMAX 800000
#define ENMAX (EMAX + NMAX)
#define EPSBN 1e-5f
#define QLEV 16256.0f      // 127*128: two-digit int8 range

// ---------------- scratch (device globals; zero-initialized; no allocation) ----------------
// g_h padded by 128 rows so WMMA tail-tile stores never leave the symbol
__device__ __align__(16) float g_h   [(size_t)(NMAX + 128) * CMAX];
__device__ __align__(16) float g_agg [(size_t)NMAX * CMAX];
__device__ __align__(16) signed char g_B2[1114112 + 1024];     // 3 layers of [d1|d0] int8 (N-major)
__device__ __align__(16) float g_dinv[NMAX];
__device__ __align__(16) float g_sa  [NMAX];                   // per-row quant scale (folded into gather)
__device__ __align__(16) float g_isa [NMAX];                   // inverse scale (used by GEMM quantizer)
__device__ __align__(16) int   g_deg [NMAX];                   // count (degree-1); reset by k_rowptr
__device__ __align__(16) int   g_rowptr[NMAX + 1];
__device__ __align__(16) int   g_cursor[NMAX];
__device__ __align__(16) int2  g_csrp[ENMAX];                  // (src, bits(dinv[src]))
__device__ __align__(16) int   g_bsum[256];
__device__ __align__(16) int   g_bpre[256];
__device__ __align__(16) float g_sum  [CMAX];                  // zeroed by k_finalize after use
__device__ __align__(16) float g_sumsq[CMAX];
__device__ __align__(16) float g_scale[CMAX];
__device__ __align__(16) float g_shift[CMAX];

// ---------------- degree count ----------------
__global__ void k_deg_count(const int* __restrict__ dst, int* __restrict__ deg, int E) {
    int i = blockIdx.x * blockDim.x + threadIdx.x;
    if (i < E) atomicAdd(&deg[dst[i]], 1);
}

// ---------------- blocksum + dinv (degree = count + 1) ----------------
__global__ void k_blocksum_dinv(const int* __restrict__ deg, int* __restrict__ bsum,
                                float* __restrict__ dinv, int n) {
    __shared__ int s[256];
    int i = blockIdx.x * 256 + threadIdx.x;
    int d = 0;
    if (i < n) {
        d = deg[i] + 1;
        dinv[i] = rsqrtf((float)d);
    }
    s[threadIdx.x] = d;
    __syncthreads();
    for (int off = 128; off > 0; off >>= 1) {
        if (threadIdx.x < off) s[threadIdx.x] += s[threadIdx.x + off];
        __syncthreads();
    }
    if (threadIdx.x == 0) bsum[blockIdx.x] = s[0];
}
__global__ void k_scanb(const int* __restrict__ bsum, int* __restrict__ bpre, int nb) {
    __shared__ int s[256];
    int t = threadIdx.x;
    int v = (t < nb) ? bsum[t] : 0;
    s[t] = v;
    __syncthreads();
    for (int off = 1; off < 256; off <<= 1) {
        int u = (t >= off) ? s[t - off] : 0;
        __syncthreads();
        s[t] += u;
        __syncthreads();
    }
    if (t < nb) bpre[t] = s[t] - v;   // exclusive
}
__global__ void k_rowptr(int* __restrict__ deg, const int* __restrict__ bpre,
                         int* __restrict__ rowptr, int* __restrict__ cursor, int n) {
    __shared__ int s[256];
    int i = blockIdx.x * 256 + threadIdx.x;
    int t = threadIdx.x;
    int v = (i < n) ? deg[i] + 1 : 0;
    s[t] = v;
    __syncthreads();
    for (int off = 1; off < 256; off <<= 1) {
        int u = (t >= off) ? s[t - off] : 0;
        __syncthreads();
        s[t] += u;
        __syncthreads();
    }
    int excl = s[t] - v + bpre[blockIdx.x];
    if (i < n) { rowptr[i] = excl; cursor[i] = excl; deg[i] = 0; }
    if (i == n - 1) rowptr[n] = excl + v;
}

// ---------------- CSR fill (edges + self-loops), packed (src, dinv[src]) ----------------
__global__ void k_csr_fill(const int* __restrict__ esrc, const int* __restrict__ edst,
                           const float* __restrict__ dinv, int* __restrict__ cursor,
                           int2* __restrict__ csrp, int E, int n) {
    int i = blockIdx.x * blockDim.x + threadIdx.x;
    if (i >= E + n) return;
    int s, d;
    if (i < E) { s = esrc[i]; d = edst[i]; }
    else       { s = d = i - E; }
    int pos = atomicAdd(&cursor[d], 1);
    csrp[pos] = make_int2(s, __float_as_int(dinv[s]));
}

// ---------------- weight quantization: per-column two-digit int8, one warp per column ----------------
// layout per layer: row nn = [d1 (K bytes) | d0 (K bytes)]
__global__ void k_wquant_all(const float* __restrict__ W1, const float* __restrict__ W2,
                             const float* __restrict__ W3, signed char* __restrict__ B2) {
    int gw = (blockIdx.x * 256 + threadIdx.x) >> 5;
    int lane = threadIdx.x & 31;
    if (gw >= 896) return;
    const float* W; int K, N, nn; size_t base;
    if (gw < 512)      { W = W1; K = 768; N = 512; nn = gw;       base = 0; }
    else if (gw < 768) { W = W2; K = 512; N = 256; nn = gw - 512; base = 786432; }
    else               { W = W3; K = 256; N = 128; nn = gw - 768; base = 1048576; }
    float mx = 0.f;
    for (int kk = lane; kk < K; kk += 32) mx = fmaxf(mx, fabsf(W[(size_t)kk * N + nn]));
#pragma unroll
    for (int off = 16; off > 0; off >>= 1)
        mx = fmaxf(mx, __shfl_xor_sync(0xFFFFFFFF, mx, off));
    float inv = (mx > 0.f) ? (QLEV / mx) : 0.f;
    signed char* d1 = B2 + base + (size_t)nn * 2 * K;
    signed char* d0 = d1 + K;
    for (int kk = lane; kk < K; kk += 32) {
        int q = __float2int_rn(W[(size_t)kk * N + nn] * inv);
        int b1 = (q + 64) >> 7;
        int b0 = q - (b1 << 7);
        d1[kk] = (signed char)b1;
        d0[kk] = (signed char)b0;
    }
}

// ---------------- per-row max -> sa/isa (one warp per row; optional fused BN+ReLU) ----------------
__global__ void k_rowmax(const float* __restrict__ in, const float* __restrict__ sc,
                         const float* __restrict__ sh, float* __restrict__ sa,
                         float* __restrict__ isa, int n, int K, int fuse) {
    int row = blockIdx.x * 8 + (threadIdx.x >> 5);
    int lane = threadIdx.x & 31;
    if (row >= n) return;
    const float* p = in + (size_t)row * K;
    float mx = 0.f;
    for (int k = lane; k < K; k += 32) {
        float v = p[k];
        if (fuse) v = fmaxf(fmaf(v, sc[k], sh[k]), 0.f);
        mx = fmaxf(mx, fabsf(v));
    }
#pragma unroll
    for (int off = 16; off > 0; off >>= 1)
        mx = fmaxf(mx, __shfl_xor_sync(0xFFFFFFFF, mx, off));
    if (lane == 0) {
        sa[row] = mx * (1.0f / QLEV);
        isa[row] = (mx > 0.f) ? (QLEV / mx) : 0.f;
    }
}

// ---------------- int8 two-digit WMMA GEMM, fused BN+ReLU+quantize on A ----------------
// h' = 16384*Sum(a1*b1) + 128*Sum(a1*b0 + a0*b1)   (a0*b0 dropped, ~1.5e-5 rel)
// True h = sa[m]*sb[n]*h'; sb folds through BatchNorm, sa folds into gather weights.
// Block 128x64, 8 warps of 32x32, BK=32; 48B padded rows; 2-stage cp.async for B.
#define BKI 32
#define RSTR 48
#define SA1_OFF 0
#define SA0_OFF 6144
#define SB1_OFF 12288
#define SB0_OFF 15360
#define STAGE_I 18432
#define SMEM_I8 (2 * STAGE_I + 2 * KMAX * 4)

__device__ __forceinline__ uint32_t smem_u32(const void* p) {
    uint32_t a;
    asm("{ .reg .u64 t; cvta.to.shared.u64 t, %1; cvt.u32.u64 %0, t; }" : "=r"(a) : "l"(p));
    return a;
}
#define CPASYNC16(dst, src) \
    asm volatile("cp.async.cg.shared.global [%0], [%1], 16;" :: "r"(dst), "l"(src) : "memory")
#define CP_COMMIT() asm volatile("cp.async.commit_group;" ::: "memory")

__global__ __launch_bounds__(256, 2)
void k_gemm_i8(const float* __restrict__ Ain, const signed char* __restrict__ Bt,
               float* __restrict__ C, const float* __restrict__ isa,
               int M, int N, int K,
               const float* __restrict__ scale, const float* __restrict__ shift, int fuse) {
    extern __shared__ __align__(16) char smem[];
    const uint32_t sb = smem_u32(smem);
    float* sscale = (float*)(smem + 2 * STAGE_I);
    float* sshift = sscale + KMAX;

    const int tid = threadIdx.x;
    const int w   = tid >> 5;
    const int m0  = blockIdx.y * 128;
    const int n0  = blockIdx.x * 64;
    const int wm  = w & 3;             // 4 m-subtiles of 32
    const int wn  = w >> 2;            // 2 n-subtiles of 32
    const size_t K2 = 2 * (size_t)K;

    const int r   = tid >> 1;          // A row 0..127
    const int seg = tid & 1;           // 16 k-elems per seg
    const bool arow_ok = (m0 + r) < M;
    const float isa_r = arow_ok ? isa[m0 + r] : 0.f;

    // B fill mapping: 64 rows x (2 planes x 2 halves)
    const int br  = tid >> 2;          // 0..63
    const int bs  = tid & 3;           // 0,1: plane1 halves; 2,3: plane0 halves

    if (fuse) {
        for (int i = tid; i < K; i += 256) { sscale[i] = scale[i]; sshift[i] = shift[i]; }
    }

    wmma::fragment<wmma::accumulator, 16, 16, 16, int> acc14[2][2], acc7[2][2];
#pragma unroll
    for (int i = 0; i < 2; i++)
#pragma unroll
        for (int j = 0; j < 2; j++) { wmma::fill_fragment(acc14[i][j], 0); wmma::fill_fragment(acc7[i][j], 0); }

    const int nch = K / BKI;
    float4 ar[4];

    auto ldgA = [&](int c) {
        const float4* gA = (const float4*)(Ain + (size_t)(m0 + r) * K + c * BKI + seg * 16);
#pragma unroll
        for (int q = 0; q < 4; q++)
            ar[q] = arow_ok ? gA[q] : make_float4(0.f, 0.f, 0.f, 0.f);
    };
    auto fillB = [&](int c, int st) {
        const signed char* gB = Bt + (size_t)(n0 + br) * K2 + ((bs < 2) ? 0 : (size_t)K)
                              + c * BKI + (bs & 1) * 16;
        uint32_t dst = sb + st * STAGE_I + ((bs < 2) ? SB1_OFF : SB0_OFF)
                     + br * RSTR + (bs & 1) * 16;
        CPASYNC16(dst, gB);
    };
    auto cvtStsA = [&](int c, int st) {
        uint32_t u1[4], u0[4];
#pragma unroll
        for (int q = 0; q < 4; q++) {
            float4 v = ar[q];
            if (fuse) {
                int kidx = c * BKI + seg * 16 + q * 4;
                float4 sc = *(float4*)&sscale[kidx];
                float4 sh = *(float4*)&sshift[kidx];
                v.x = fmaxf(fmaf(v.x, sc.x, sh.x), 0.f);
                v.y = fmaxf(fmaf(v.y, sc.y, sh.y), 0.f);
                v.z = fmaxf(fmaf(v.z, sc.z, sh.z), 0.f);
                v.w = fmaxf(fmaf(v.w, sc.w, sh.w), 0.f);
            }
            int qx = __float2int_rn(v.x * isa_r);
            int qy = __float2int_rn(v.y * isa_r);
            int qz = __float2int_rn(v.z * isa_r);
            int qw = __float2int_rn(v.w * isa_r);
            int hx = (qx + 64) >> 7, hy = (qy + 64) >> 7, hz = (qz + 64) >> 7, hw = (qw + 64) >> 7;
            int lx = qx - (hx << 7), ly = qy - (hy << 7), lz = qz - (hz << 7), lw = qw - (hw << 7);
            u1[q] = (hx & 0xFF) | ((hy & 0xFF) << 8) | ((hz & 0xFF) << 16) | ((hw & 0xFF) << 24);
            u0[q] = (lx & 0xFF) | ((ly & 0xFF) << 8) | ((lz & 0xFF) << 16) | ((lw & 0xFF) << 24);
        }
        uint32_t o = r * RSTR + seg * 16;
        *(uint4*)(smem + st * STAGE_I + SA1_OFF + o) = make_uint4(u1[0], u1[1], u1[2], u1[3]);
        *(uint4*)(smem + st * STAGE_I + SA0_OFF + o) = make_uint4(u0[0], u0[1], u0[2], u0[3]);
    };

    // --- prologue ---
    ldgA(0);
    fillB(0, 0);
    CP_COMMIT();
    __syncthreads();          // scale/shift table visible before conversion
    cvtStsA(0, 0);

    for (int c = 0; c < nch; c++) {
        int cur = c & 1;
        asm volatile("cp.async.wait_group 0;" ::: "memory");   // B for chunk c arrived
        __syncthreads();   // A STS for chunk c visible; stage cur^1 retired

        if (c + 1 < nch) {
            ldgA(c + 1);
            fillB(c + 1, cur ^ 1);
            CP_COMMIT();
        }

        const signed char* sA1 = (const signed char*)(smem + cur * STAGE_I + SA1_OFF);
        const signed char* sA0 = (const signed char*)(smem + cur * STAGE_I + SA0_OFF);
        const signed char* sB1 = (const signed char*)(smem + cur * STAGE_I + SB1_OFF);
        const signed char* sB0 = (const signed char*)(smem + cur * STAGE_I + SB0_OFF);

#pragma unroll
        for (int kk = 0; kk < BKI; kk += 16) {
            wmma::fragment<wmma::matrix_a, 16, 16, 16, signed char, wmma::row_major> a1f[2], a0f[2];
            wmma::fragment<wmma::matrix_b, 16, 16, 16, signed char, wmma::col_major> b1f[2], b0f[2];
            // term 1: a1 x b1 -> acc14
#pragma unroll
            for (int i = 0; i < 2; i++)
                wmma::load_matrix_sync(a1f[i], sA1 + (wm * 32 + i * 16) * RSTR + kk, RSTR);
#pragma unroll
            for (int j = 0; j < 2; j++)
                wmma::load_matrix_sync(b1f[j], sB1 + (wn * 32 + j * 16) * RSTR + kk, RSTR);
#pragma unroll
            for (int i = 0; i < 2; i++)
#pragma unroll
                for (int j = 0; j < 2; j++)
                    wmma::mma_sync(acc14[i][j], a1f[i], b1f[j], acc14[i][j]);
            // term 2: a0 x b1 -> acc7 (reuse b1f)
#pragma unroll
            for (int i = 0; i < 2; i++)
                wmma::load_matrix_sync(a0f[i], sA0 + (wm * 32 + i * 16) * RSTR + kk, RSTR);
#pragma unroll
            for (int i = 0; i < 2; i++)
#pragma unroll
                for (int j = 0; j < 2; j++)
                    wmma::mma_sync(acc7[i][j], a0f[i], b1f[j], acc7[i][j]);
            // term 3: a1 x b0 -> acc7 (reuse a1f)
#pragma unroll
            for (int j = 0; j < 2; j++)
                wmma::load_matrix_sync(b0f[j], sB0 + (wn * 32 + j * 16) * RSTR + kk, RSTR);
#pragma unroll
            for (int i = 0; i < 2; i++)
#pragma unroll
                for (int j = 0; j < 2; j++)
                    wmma::mma_sync(acc7[i][j], a1f[i], b0f[j], acc7[i][j]);
        }

        if (c + 1 < nch) cvtStsA(c + 1, cur ^ 1);   // visible at next iteration's sync
    }

    // epilogue: combine digit accumulators elementwise (s32/f32 acc frags share layout)
#pragma unroll
    for (int i = 0; i < 2; i++)
#pragma unroll
        for (int j = 0; j < 2; j++) {
            wmma::fragment<wmma::accumulator, 16, 16, 16, float> f;
#pragma unroll
            for (int e = 0; e < f.num_elements; e++)
                f.x[e] = (float)acc14[i][j].x[e] * 16384.0f + (float)acc7[i][j].x[e] * 128.0f;
            wmma::store_matrix_sync(C + (size_t)(m0 + wm * 32 + i * 16) * N + n0 + wn * 32 + j * 16,
                                    f, N, wmma::mem_row_major);
        }
}

// ---------------- CSR gather: one thread per (row, c4); weight includes sa[src] ----------------
__global__ __launch_bounds__(256)
void k_gather(const int* __restrict__ rowptr, const int2* __restrict__ csrp,
              const float* __restrict__ dinv, const float* __restrict__ sa,
              const float* __restrict__ h, float* __restrict__ agg, int n, int C) {
    const int tpr = C >> 2;
    const int rpb = 256 / tpr;
    int tid = threadIdx.x;
    int row = blockIdx.x * rpb + tid / tpr;
    int c4  = tid % tpr;
    if (row >= n) return;
    int jb = rowptr[row], je = rowptr[row + 1];
    const float4* h4 = (const float4*)h;
    float4 acc = make_float4(0.f, 0.f, 0.f, 0.f);
    int j = jb;
    for (; j + 4 <= je; j += 4) {
        int2 p0 = csrp[j], p1 = csrp[j + 1], p2 = csrp[j + 2], p3 = csrp[j + 3];
        float4 v0 = h4[(size_t)p0.x * tpr + c4];
        float4 v1 = h4[(size_t)p1.x * tpr + c4];
        float4 v2 = h4[(size_t)p2.x * tpr + c4];
        float4 v3 = h4[(size_t)p3.x * tpr + c4];
        float w0 = __int_as_float(p0.y) * sa[p0.x];
        float w1 = __int_as_float(p1.y) * sa[p1.x];
        float w2 = __int_as_float(p2.y) * sa[p2.x];
        float w3 = __int_as_float(p3.y) * sa[p3.x];
        acc.x = fmaf(w0, v0.x, fmaf(w1, v1.x, fmaf(w2, v2.x, fmaf(w3, v3.x, acc.x))));
        acc.y = fmaf(w0, v0.y, fmaf(w1, v1.y, fmaf(w2, v2.y, fmaf(w3, v3.y, acc.y))));
        acc.z = fmaf(w0, v0.z, fmaf(w1, v1.z, fmaf(w2, v2.z, fmaf(w3, v3.z, acc.z))));
        acc.w = fmaf(w0, v0.w, fmaf(w1, v1.w, fmaf(w2, v2.w, fmaf(w3, v3.w, acc.w))));
    }
    for (; j < je; j++) {
        int2 p = csrp[j];
        float wgt = __int_as_float(p.y) * sa[p.x];
        float4 v = h4[(size_t)p.x * tpr + c4];
        acc.x = fmaf(wgt, v.x, acc.x);
        acc.y = fmaf(wgt, v.y, acc.y);
        acc.z = fmaf(wgt, v.z, acc.z);
        acc.w = fmaf(wgt, v.w, acc.w);
    }
    float dd = dinv[row];
    acc.x *= dd; acc.y *= dd; acc.z *= dd; acc.w *= dd;
    ((float4*)agg)[(size_t)row * tpr + c4] = acc;
}

// ---------------- column stats ----------------
__global__ void k_colstats(const float* __restrict__ agg, int n, int C, int rows_per,
                           float* __restrict__ sum, float* __restrict__ sumsq) {
    int c = blockIdx.x * blockDim.x + threadIdx.x;
    int r0 = blockIdx.y * rows_per;
    int r1 = r0 + rows_per; if (r1 > n) r1 = n;
    float s = 0.f, ss = 0.f;
    for (int r = r0; r < r1; r++) {
        float v = agg[(size_t)r * C + c];
        s += v; ss += v * v;
    }
    atomicAdd(&sum[c], s);
    atomicAdd(&sumsq[c], ss);
}

// ---------------- finalize (also zeroes stats for next layer / replay) ----------------
__global__ void k_finalize(float* __restrict__ sum, float* __restrict__ sumsq,
                           const float* __restrict__ gam, const float* __restrict__ bet,
                           float* __restrict__ scale, float* __restrict__ shift,
                           int n, int C) {
    int c = threadIdx.x;   // <<<1, CMAX>>>
    if (c < C) {
        float inv_n = 1.0f / (float)n;
        float m  = sum[c] * inv_n;
        float v  = sumsq[c] * inv_n - m * m;
        float rs = rsqrtf(v + EPSBN);
        float sc = gam[c] * rs;
        scale[c] = sc;
        shift[c] = bet[c] - m * sc;
    }
    sum[c] = 0.f;
    sumsq[c] = 0.f;
}
__global__ void k_bn_apply(const float* __restrict__ agg, const float* __restrict__ scale,
                           const float* __restrict__ shift, float* __restrict__ out,
                           int n, int C) {
    int i4 = blockIdx.x * blockDim.x + threadIdx.x;
    int tot4 = (n * C) >> 2;
    if (i4 >= tot4) return;
    int c = (i4 % (C >> 2)) << 2;
    float4 v = ((const float4*)agg)[i4];
    v.x = fmaf(v.x, scale[c + 0], shift[c + 0]);
    v.y = fmaf(v.y, scale[c + 1], shift[c + 1]);
    v.z = fmaf(v.z, scale[c + 2], shift[c + 2]);
    v.w = fmaf(v.w, scale[c + 3], shift[c + 3]);
    ((float4*)out)[i4] = v;
}

// ---------------- host orchestration ----------------
extern "C" void kernel_launch(void* const* d_in, const int* in_sizes, int n_in,
                              void* d_out, int out_size) {
    const float* x  = (const float*)d_in[0];
    const int*   ei = (const int*)d_in[1];          // int32 (JAX x64 disabled)
    const float* W1 = (const float*)d_in[2];
    const float* g1 = (const float*)d_in[4];
    const float* be1 = (const float*)d_in[5];
    const float* W2 = (const float*)d_in[6];
    const float* g2 = (const float*)d_in[8];
    const float* be2 = (const float*)d_in[9];
    const float* W3 = (const float*)d_in[10];
    const float* g3 = (const float*)d_in[12];
    const float* be3 = (const float*)d_in[13];

    int n = in_sizes[0] / 768;
    int E = in_sizes[1] / 2;
    const int* esrc = ei;
    const int* edst = ei + E;

    float *hbuf, *aggbuf, *dinv, *sa, *isa, *sum, *sumsq, *scale, *shift;
    int *deg, *rowptr, *cursor, *bsum, *bpre;
    int2 *csrp;
    signed char *B2;
    cudaGetSymbolAddress((void**)&hbuf,   g_h);
    cudaGetSymbolAddress((void**)&aggbuf, g_agg);
    cudaGetSymbolAddress((void**)&B2,     g_B2);
    cudaGetSymbolAddress((void**)&dinv,   g_dinv);
    cudaGetSymbolAddress((void**)&sa,     g_sa);
    cudaGetSymbolAddress((void**)&isa,    g_isa);
    cudaGetSymbolAddress((void**)&deg,    g_deg);
    cudaGetSymbolAddress((void**)&rowptr, g_rowptr);
    cudaGetSymbolAddress((void**)&cursor, g_cursor);
    cudaGetSymbolAddress((void**)&csrp,   g_csrp);
    cudaGetSymbolAddress((void**)&bsum,   g_bsum);
    cudaGetSymbolAddress((void**)&bpre,   g_bpre);
    cudaGetSymbolAddress((void**)&sum,    g_sum);
    cudaGetSymbolAddress((void**)&sumsq,  g_sumsq);
    cudaGetSymbolAddress((void**)&scale,  g_scale);
    cudaGetSymbolAddress((void**)&shift,  g_shift);

    static int attr_done = 0;
    if (!attr_done) {
        cudaFuncSetAttribute(k_gemm_i8, cudaFuncAttributeMaxDynamicSharedMemorySize, SMEM_I8);
        attr_done = 1;
    }

    const int dims[4] = {768, 512, 256, 128};
    const float* gs[3]  = {g1, g2, g3};
    const float* bes[3] = {be1, be2, be3};
    size_t boff[3] = {0, 786432, 1048576};

    // ---- launches 1-3: weight quant, degree, layer-1 rowmax ----
    k_wquant_all<<<112, 256>>>(W1, W2, W3, B2);
    k_deg_count<<<(E + 255) / 256, 256>>>(edst, deg, E);
    k_rowmax<<<(n + 7) / 8, 256>>>(x, scale, shift, sa, isa, n, 768, 0);

    // ---- launch 4: layer-1 int8 GEMM (ncu capture slot) ----
    {
        dim3 ggrid(dims[1] / 64, (n + 127) / 128);
        k_gemm_i8<<<ggrid, 256, SMEM_I8>>>(x, B2 + boff[0], hbuf, isa, n, dims[1], dims[0],
                                           scale, shift, 0);
    }

    // ---- remaining graph prep ----
    int nb = (n + 255) / 256;
    k_blocksum_dinv<<<nb, 256>>>(deg, bsum, dinv, n);
    k_scanb<<<1, 256>>>(bsum, bpre, nb);
    k_rowptr<<<nb, 256>>>(deg, bpre, rowptr, cursor, n);
    k_csr_fill<<<(E + n + 255) / 256, 256>>>(esrc, edst, dinv, cursor, csrp, E, n);

    for (int L = 0; L < 3; L++) {
        int Cin = dims[L], Cout = dims[L + 1];

        if (L > 0) {
            // rowmax over BN+ReLU-transformed agg, then fused int8 GEMM
            k_rowmax<<<(n + 7) / 8, 256>>>(aggbuf, scale, shift, sa, isa, n, Cin, 1);
            dim3 ggrid(Cout / 64, (n + 127) / 128);
            k_gemm_i8<<<ggrid, 256, SMEM_I8>>>(aggbuf, B2 + boff[L], hbuf, isa, n, Cout, Cin,
                                               scale, shift, 1);
        }

        // CSR gather (sa folded into edge weights)
        int tpr = Cout >> 2;
        int rpb = 256 / tpr;
        k_gather<<<(n + rpb - 1) / rpb, 256>>>(rowptr, csrp, dinv, sa, hbuf, aggbuf, n, Cout);

        // BN statistics
        int rows_per = (n + 199) / 200;
        dim3 sgrid(Cout / 128, 200);
        k_colstats<<<sgrid, 128>>>(aggbuf, n, Cout, rows_per, sum, sumsq);
        k_finalize<<<1, CMAX>>>(sum, sumsq, gs[L], bes[L], scale, shift, n, Cout);
    }

    // final BN apply (no ReLU) -> d_out
    int n4 = (n * 128) >> 2;
    k_bn_apply<<<(n4 + 255) / 256, 256>>>(aggbuf, scale, shift, (float*)d_out, n, 128);
}

// round 15
// speedup vs baseline: 2.9604x; 2.9604x over previous
#include <cuda_runtime.h>
#include <cuda_bf16.h>
#include <cuda_fp16.h>
#include <mma.h>
#include <cstdint>
#include <cstddef>

using namespace nvcuda;

// Problem constants (fixed by setup_inputs)
#define NMAX 50000
#define KMAX 768
#define CMAX 512
#define EMAX 800000
#define ENMAX (EMAX + NMAX)
#define EPSBN 1e-5f

// ---------------- scratch (device globals; zero-initialized; no allocation) ----------------
// g_h padded by 128 rows so GEMM tail-tile stores never leave the symbol
__device__ __align__(16) __half g_h  [(size_t)(NMAX + 128) * CMAX];   // fp16 GEMM output
__device__ __align__(16) float g_agg [(size_t)NMAX * CMAX];
__device__ __align__(16) __nv_bfloat16 g_B2[1114112 + 1024];   // 3 layers of [hi|lo] (N-major)
__device__ __align__(16) float g_dinv[NMAX];
__device__ __align__(16) int   g_deg [NMAX];                   // count (degree-1); reset by k_rowptr
__device__ __align__(16) int   g_rowptr[NMAX + 1];
__device__ __align__(16) int   g_cursor[NMAX];
__device__ __align__(16) int2  g_csrp[ENMAX];                  // (src, bits(dinv[src]))
__device__ __align__(16) int   g_bsum[256];
__device__ __align__(16) int   g_bpre[256];
__device__ __align__(16) float g_sum  [CMAX];                  // zeroed by k_finalize after use
__device__ __align__(16) float g_sumsq[CMAX];
__device__ __align__(16) float g_scale[CMAX];
__device__ __align__(16) float g_shift[CMAX];

// ---------------- degree count ----------------
__global__ void k_deg_count(const int* __restrict__ dst, int* __restrict__ deg, int E) {
    int i = blockIdx.x * blockDim.x + threadIdx.x;
    if (i < E) atomicAdd(&deg[dst[i]], 1);
}

// ---------------- blocksum + dinv (degree = count + 1) ----------------
__global__ void k_blocksum_dinv(const int* __restrict__ deg, int* __restrict__ bsum,
                                float* __restrict__ dinv, int n) {
    __shared__ int s[256];
    int i = blockIdx.x * 256 + threadIdx.x;
    int d = 0;
    if (i < n) {
        d = deg[i] + 1;
        dinv[i] = rsqrtf((float)d);
    }
    s[threadIdx.x] = d;
    __syncthreads();
    for (int off = 128; off > 0; off >>= 1) {
        if (threadIdx.x < off) s[threadIdx.x] += s[threadIdx.x + off];
        __syncthreads();
    }
    if (threadIdx.x == 0) bsum[blockIdx.x] = s[0];
}
__global__ void k_scanb(const int* __restrict__ bsum, int* __restrict__ bpre, int nb) {
    __shared__ int s[256];
    int t = threadIdx.x;
    int v = (t < nb) ? bsum[t] : 0;
    s[t] = v;
    __syncthreads();
    for (int off = 1; off < 256; off <<= 1) {
        int u = (t >= off) ? s[t - off] : 0;
        __syncthreads();
        s[t] += u;
        __syncthreads();
    }
    if (t < nb) bpre[t] = s[t] - v;   // exclusive
}
__global__ void k_rowptr(int* __restrict__ deg, const int* __restrict__ bpre,
                         int* __restrict__ rowptr, int* __restrict__ cursor, int n) {
    __shared__ int s[256];
    int i = blockIdx.x * 256 + threadIdx.x;
    int t = threadIdx.x;
    int v = (i < n) ? deg[i] + 1 : 0;
    s[t] = v;
    __syncthreads();
    for (int off = 1; off < 256; off <<= 1) {
        int u = (t >= off) ? s[t - off] : 0;
        __syncthreads();
        s[t] += u;
        __syncthreads();
    }
    int excl = s[t] - v + bpre[blockIdx.x];
    if (i < n) { rowptr[i] = excl; cursor[i] = excl; deg[i] = 0; }
    if (i == n - 1) rowptr[n] = excl + v;
}

// ---------------- CSR fill (edges + self-loops), packed (src, dinv[src]) ----------------
__global__ void k_csr_fill(const int* __restrict__ esrc, const int* __restrict__ edst,
                           const float* __restrict__ dinv, int* __restrict__ cursor,
                           int2* __restrict__ csrp, int E, int n) {
    int i = blockIdx.x * blockDim.x + threadIdx.x;
    if (i >= E + n) return;
    int s, d;
    if (i < E) { s = esrc[i]; d = edst[i]; }
    else       { s = d = i - E; }
    int pos = atomicAdd(&cursor[d], 1);
    csrp[pos] = make_int2(s, __float_as_int(dinv[s]));
}

// ---------------- all weights: W[K][N] -> [hi|lo] bf16 transposed to [N][2K] ----------------
__global__ void k_wsplit_all(const float* __restrict__ W1, const float* __restrict__ W2,
                             const float* __restrict__ W3, __nv_bfloat16* __restrict__ B2) {
    int idx = blockIdx.x * blockDim.x + threadIdx.x;
    const float* W; int K, N; size_t boff; int local;
    if (idx < 393216)       { W = W1; K = 768; N = 512; boff = 0;      local = idx; }
    else if (idx < 524288)  { W = W2; K = 512; N = 256; boff = 786432; local = idx - 393216; }
    else if (idx < 557056)  { W = W3; K = 256; N = 128; boff = 1048576; local = idx - 524288; }
    else return;
    int nn = local / K, kk = local % K;
    float v = W[(size_t)kk * N + nn];
    __nv_bfloat16 h = __float2bfloat16(v);
    __nv_bfloat16 l = __float2bfloat16(v - __bfloat162float(h));
    size_t base = boff + (size_t)nn * 2 * K + kk;
    B2[base]     = h;
    B2[base + K] = l;
}

// ---------------- WMMA bf16 3-term GEMM, fused BN+ReLU+split on A, fp16 output ----------------
// C = Ah*Bh + Al*Bh + Ah*Bl (fp32 accum), A read as fp32, split in-kernel; h stored fp16.
#define WBK 32
#define BKP 40
#define TILE_B (128 * BKP * 2)          // 10240 bytes per tile
#define STAGE_B (4 * TILE_B)            // 40960 bytes per stage
#define SMEM_WMMA (2 * STAGE_B + 2 * KMAX * 4)
#define STG_LD 72                       // epilogue staging ld (avoids 32-way LDS conflicts)

__device__ __forceinline__ uint32_t smem_u32(const void* p) {
    uint32_t a;
    asm("{ .reg .u64 t; cvta.to.shared.u64 t, %1; cvt.u32.u64 %0, t; }" : "=r"(a) : "l"(p));
    return a;
}
__device__ __forceinline__ uint32_t h2u(__half2 h) { return *(uint32_t*)&h; }
#define CPASYNC16(dst, src) \
    asm volatile("cp.async.cg.shared.global [%0], [%1], 16;" :: "r"(dst), "l"(src) : "memory")
#define CP_COMMIT() asm volatile("cp.async.commit_group;" ::: "memory")

__global__ __launch_bounds__(256, 2)
void k_wmma(const float* __restrict__ Ain, const __nv_bfloat16* __restrict__ Bt,
            __half* __restrict__ C, int M, int N, int K,
            const float* __restrict__ scale, const float* __restrict__ shift, int fuse) {
    extern __shared__ __align__(16) char smem[];
    const uint32_t sb = smem_u32(smem);
    float* sscale = (float*)(smem + 2 * STAGE_B);
    float* sshift = sscale + KMAX;

    const int tid = threadIdx.x;
    const int w   = tid >> 5;
    const int lane = tid & 31;
    const int m0  = blockIdx.y * 128;
    const int n0  = blockIdx.x * 128;
    const int wm  = w & 3;
    const int wn  = w >> 2;
    const size_t K2 = 2 * (size_t)K;

    const int r   = tid >> 1;          // 0..127 (row within tile)
    const int seg = tid & 1;           // half-row of 16 elems
    const bool arow_ok = (m0 + r) < M;

    if (fuse) {
        for (int i = tid; i < K; i += 256) { sscale[i] = scale[i]; sshift[i] = shift[i]; }
    }

    wmma::fragment<wmma::accumulator, 16, 16, 16, float> acc[2][4];
#pragma unroll
    for (int i = 0; i < 2; i++)
#pragma unroll
        for (int j = 0; j < 4; j++) wmma::fill_fragment(acc[i][j], 0.0f);

    const int nch = K / WBK;
    float4 ar[4];

    auto ldgA = [&](int c) {
        const float4* gA = (const float4*)(Ain + (size_t)(m0 + r) * K + c * WBK + seg * 16);
#pragma unroll
        for (int q = 0; q < 4; q++)
            ar[q] = arow_ok ? gA[q] : make_float4(0.f, 0.f, 0.f, 0.f);
    };
    auto fillB = [&](int c, int st) {
        uint32_t base = sb + st * STAGE_B + r * (BKP * 2);
        const __nv_bfloat16* gB = Bt + (size_t)(n0 + r) * K2 + c * WBK + seg * 16;
#pragma unroll
        for (int q = 0; q < 2; q++) {
            uint32_t o = (seg * 2 + q) * 16;
            CPASYNC16(base + 2 * TILE_B + o, gB + q * 8);        // B hi
            CPASYNC16(base + 3 * TILE_B + o, gB + K + q * 8);    // B lo
        }
    };
    auto cvtStsA = [&](int c, int st) {
        __nv_bfloat16* sAh = (__nv_bfloat16*)(smem + st * STAGE_B + 0 * TILE_B);
        __nv_bfloat16* sAl = (__nv_bfloat16*)(smem + st * STAGE_B + 1 * TILE_B);
        int off = r * BKP + seg * 16;
#pragma unroll
        for (int q = 0; q < 4; q++) {
            float4 v = ar[q];
            if (fuse) {
                int kidx = c * WBK + seg * 16 + q * 4;
                float4 sc = *(float4*)&sscale[kidx];
                float4 sh = *(float4*)&sshift[kidx];
                v.x = fmaxf(fmaf(v.x, sc.x, sh.x), 0.f);
                v.y = fmaxf(fmaf(v.y, sc.y, sh.y), 0.f);
                v.z = fmaxf(fmaf(v.z, sc.z, sh.z), 0.f);
                v.w = fmaxf(fmaf(v.w, sc.w, sh.w), 0.f);
            }
            __nv_bfloat16 h0 = __float2bfloat16(v.x), h1 = __float2bfloat16(v.y);
            __nv_bfloat16 h2 = __float2bfloat16(v.z), h3 = __float2bfloat16(v.w);
            __nv_bfloat16 l0 = __float2bfloat16(v.x - __bfloat162float(h0));
            __nv_bfloat16 l1 = __float2bfloat16(v.y - __bfloat162float(h1));
            __nv_bfloat16 l2 = __float2bfloat16(v.z - __bfloat162float(h2));
            __nv_bfloat16 l3 = __float2bfloat16(v.w - __bfloat162float(h3));
            uint2 uh, ul;
            uh.x = (uint32_t)__bfloat16_as_ushort(h0) | ((uint32_t)__bfloat16_as_ushort(h1) << 16);
            uh.y = (uint32_t)__bfloat16_as_ushort(h2) | ((uint32_t)__bfloat16_as_ushort(h3) << 16);
            ul.x = (uint32_t)__bfloat16_as_ushort(l0) | ((uint32_t)__bfloat16_as_ushort(l1) << 16);
            ul.y = (uint32_t)__bfloat16_as_ushort(l2) | ((uint32_t)__bfloat16_as_ushort(l3) << 16);
            *(uint2*)(sAh + off + q * 4) = uh;
            *(uint2*)(sAl + off + q * 4) = ul;
        }
    };

    // --- prologue ---
    ldgA(0);
    fillB(0, 0);
    CP_COMMIT();
    __syncthreads();          // scale/shift table visible before conversion
    cvtStsA(0, 0);

    for (int c = 0; c < nch; c++) {
        int cur = c & 1;
        asm volatile("cp.async.wait_group 0;" ::: "memory");   // B for chunk c arrived
        __syncthreads();   // A STS for chunk c visible; stage cur^1 retired

        if (c + 1 < nch) {
            ldgA(c + 1);
            fillB(c + 1, cur ^ 1);
            CP_COMMIT();
        }

        const __nv_bfloat16* sAh = (const __nv_bfloat16*)(smem + cur * STAGE_B + 0 * TILE_B);
        const __nv_bfloat16* sAl = (const __nv_bfloat16*)(smem + cur * STAGE_B + 1 * TILE_B);
        const __nv_bfloat16* sBh = (const __nv_bfloat16*)(smem + cur * STAGE_B + 2 * TILE_B);
        const __nv_bfloat16* sBl = (const __nv_bfloat16*)(smem + cur * STAGE_B + 3 * TILE_B);

#pragma unroll
        for (int kk = 0; kk < WBK; kk += 16) {
            wmma::fragment<wmma::matrix_a, 16, 16, 16, __nv_bfloat16, wmma::row_major> afH[2], afL[2];
            wmma::fragment<wmma::matrix_b, 16, 16, 16, __nv_bfloat16, wmma::col_major> bfH[4], bfL[4];
            // term 1: Ah x Bh
#pragma unroll
            for (int i = 0; i < 2; i++)
                wmma::load_matrix_sync(afH[i], sAh + (wm * 32 + i * 16) * BKP + kk, BKP);
#pragma unroll
            for (int j = 0; j < 4; j++)
                wmma::load_matrix_sync(bfH[j], sBh + (wn * 64 + j * 16) * BKP + kk, BKP);
#pragma unroll
            for (int i = 0; i < 2; i++)
#pragma unroll
                for (int j = 0; j < 4; j++)
                    wmma::mma_sync(acc[i][j], afH[i], bfH[j], acc[i][j]);
            // term 2: Al x Bh (reuse bfH)
#pragma unroll
            for (int i = 0; i < 2; i++)
                wmma::load_matrix_sync(afL[i], sAl + (wm * 32 + i * 16) * BKP + kk, BKP);
#pragma unroll
            for (int i = 0; i < 2; i++)
#pragma unroll
                for (int j = 0; j < 4; j++)
                    wmma::mma_sync(acc[i][j], afL[i], bfH[j], acc[i][j]);
            // term 3: Ah x Bl (reuse afH)
#pragma unroll
            for (int j = 0; j < 4; j++)
                wmma::load_matrix_sync(bfL[j], sBl + (wn * 64 + j * 16) * BKP + kk, BKP);
#pragma unroll
            for (int i = 0; i < 2; i++)
#pragma unroll
                for (int j = 0; j < 4; j++)
                    wmma::mma_sync(acc[i][j], afH[i], bfL[j], acc[i][j]);
        }

        if (c + 1 < nch) cvtStsA(c + 1, cur ^ 1);   // visible at next iteration's sync
    }

    // --- epilogue: stage fp32 accs through (retired) pipeline smem, emit fp16 ---
    __syncthreads();   // everyone done reading the stage buffers
    float* stg = (float*)smem + w * (32 * STG_LD);   // 8 warps x 9216B = 73.7KB < 80KB
#pragma unroll
    for (int i = 0; i < 2; i++)
#pragma unroll
        for (int j = 0; j < 4; j++)
            wmma::store_matrix_sync(stg + (i * 16) * STG_LD + j * 16, acc[i][j],
                                    STG_LD, wmma::mem_row_major);
    __syncwarp();
    {
        const float* srow = stg + lane * STG_LD;
        __half* drow = C + (size_t)(m0 + wm * 32 + lane) * N + n0 + wn * 64;
        // g_h is padded by 128 rows; tail-tile overrun harmless, never read
#pragma unroll
        for (int q = 0; q < 8; q++) {
            float4 fa = *(const float4*)(srow + q * 8);
            float4 fb = *(const float4*)(srow + q * 8 + 4);
            uint4 o;
            o.x = h2u(__floats2half2_rn(fa.x, fa.y));
            o.y = h2u(__floats2half2_rn(fa.z, fa.w));
            o.z = h2u(__floats2half2_rn(fb.x, fb.y));
            o.w = h2u(__floats2half2_rn(fb.z, fb.w));
            *(uint4*)(drow + q * 8) = o;
        }
    }
}

// ---------------- CSR gather: one thread per (row, c4); fp16 h, fp32 accum ----------------
__global__ __launch_bounds__(256)
void k_gather(const int* __restrict__ rowptr, const int2* __restrict__ csrp,
              const float* __restrict__ dinv,
              const __half* __restrict__ h, float* __restrict__ agg, int n, int C) {
    const int tpr = C >> 2;                 // 4 halves (one uint2) per thread
    const int rpb = 256 / tpr;
    int tid = threadIdx.x;
    int row = blockIdx.x * rpb + tid / tpr;
    int c4  = tid % tpr;
    if (row >= n) return;
    int jb = rowptr[row], je = rowptr[row + 1];
    const uint2* h2p = (const uint2*)h;
    float4 acc = make_float4(0.f, 0.f, 0.f, 0.f);
    int j = jb;
    for (; j + 4 <= je; j += 4) {
        int2 p0 = csrp[j], p1 = csrp[j + 1], p2 = csrp[j + 2], p3 = csrp[j + 3];
        uint2 u0 = h2p[(size_t)p0.x * tpr + c4];
        uint2 u1 = h2p[(size_t)p1.x * tpr + c4];
        uint2 u2 = h2p[(size_t)p2.x * tpr + c4];
        uint2 u3 = h2p[(size_t)p3.x * tpr + c4];
        float w0 = __int_as_float(p0.y), w1 = __int_as_float(p1.y);
        float w2 = __int_as_float(p2.y), w3 = __int_as_float(p3.y);
        float2 a0 = __half22float2(*(__half2*)&u0.x), b0 = __half22float2(*(__half2*)&u0.y);
        float2 a1 = __half22float2(*(__half2*)&u1.x), b1 = __half22float2(*(__half2*)&u1.y);
        float2 a2 = __half22float2(*(__half2*)&u2.x), b2 = __half22float2(*(__half2*)&u2.y);
        float2 a3 = __half22float2(*(__half2*)&u3.x), b3 = __half22float2(*(__half2*)&u3.y);
        acc.x = fmaf(w0, a0.x, fmaf(w1, a1.x, fmaf(w2, a2.x, fmaf(w3, a3.x, acc.x))));
        acc.y = fmaf(w0, a0.y, fmaf(w1, a1.y, fmaf(w2, a2.y, fmaf(w3, a3.y, acc.y))));
        acc.z = fmaf(w0, b0.x, fmaf(w1, b1.x, fmaf(w2, b2.x, fmaf(w3, b3.x, acc.z))));
        acc.w = fmaf(w0, b0.y, fmaf(w1, b1.y, fmaf(w2, b2.y, fmaf(w3, b3.y, acc.w))));
    }
    for (; j < je; j++) {
        int2 p = csrp[j];
        float wgt = __int_as_float(p.y);
        uint2 u = h2p[(size_t)p.x * tpr + c4];
        float2 a = __half22float2(*(__half2*)&u.x);
        float2 b = __half22float2(*(__half2*)&u.y);
        acc.x = fmaf(wgt, a.x, acc.x);
        acc.y = fmaf(wgt, a.y, acc.y);
        acc.z = fmaf(wgt, b.x, acc.z);
        acc.w = fmaf(wgt, b.y, acc.w);
    }
    float dd = dinv[row];
    acc.x *= dd; acc.y *= dd; acc.z *= dd; acc.w *= dd;
    ((float4*)agg)[(size_t)row * tpr + c4] = acc;
}

// ---------------- column stats ----------------
__global__ void k_colstats(const float* __restrict__ agg, int n, int C, int rows_per,
                           float* __restrict__ sum, float* __restrict__ sumsq) {
    int c = blockIdx.x * blockDim.x + threadIdx.x;
    int r0 = blockIdx.y * rows_per;
    int r1 = r0 + rows_per; if (r1 > n) r1 = n;
    float s = 0.f, ss = 0.f;
    for (int r = r0; r < r1; r++) {
        float v = agg[(size_t)r * C + c];
        s += v; ss += v * v;
    }
    atomicAdd(&sum[c], s);
    atomicAdd(&sumsq[c], ss);
}

// ---------------- finalize (also zeroes stats for next layer / replay) ----------------
__global__ void k_finalize(float* __restrict__ sum, float* __restrict__ sumsq,
                           const float* __restrict__ gam, const float* __restrict__ bet,
                           float* __restrict__ scale, float* __restrict__ shift,
                           int n, int C) {
    int c = threadIdx.x;   // <<<1, CMAX>>>
    if (c < C) {
        float inv_n = 1.0f / (float)n;
        float m  = sum[c] * inv_n;
        float v  = sumsq[c] * inv_n - m * m;
        float rs = rsqrtf(v + EPSBN);
        float sc = gam[c] * rs;
        scale[c] = sc;
        shift[c] = bet[c] - m * sc;
    }
    sum[c] = 0.f;
    sumsq[c] = 0.f;
}
__global__ void k_bn_apply(const float* __restrict__ agg, const float* __restrict__ scale,
                           const float* __restrict__ shift, float* __restrict__ out,
                           int n, int C) {
    int i4 = blockIdx.x * blockDim.x + threadIdx.x;
    int tot4 = (n * C) >> 2;
    if (i4 >= tot4) return;
    int c = (i4 % (C >> 2)) << 2;
    float4 v = ((const float4*)agg)[i4];
    v.x = fmaf(v.x, scale[c + 0], shift[c + 0]);
    v.y = fmaf(v.y, scale[c + 1], shift[c + 1]);
    v.z = fmaf(v.z, scale[c + 2], shift[c + 2]);
    v.w = fmaf(v.w, scale[c + 3], shift[c + 3]);
    ((float4*)out)[i4] = v;
}

// ---------------- host orchestration ----------------
extern "C" void kernel_launch(void* const* d_in, const int* in_sizes, int n_in,
                              void* d_out, int out_size) {
    const float* x  = (const float*)d_in[0];
    const int*   ei = (const int*)d_in[1];          // int32 (JAX x64 disabled)
    const float* W1 = (const float*)d_in[2];
    const float* g1 = (const float*)d_in[4];
    const float* be1 = (const float*)d_in[5];
    const float* W2 = (const float*)d_in[6];
    const float* g2 = (const float*)d_in[8];
    const float* be2 = (const float*)d_in[9];
    const float* W3 = (const float*)d_in[10];
    const float* g3 = (const float*)d_in[12];
    const float* be3 = (const float*)d_in[13];

    int n = in_sizes[0] / 768;
    int E = in_sizes[1] / 2;
    const int* esrc = ei;
    const int* edst = ei + E;

    float *aggbuf, *dinv, *sum, *sumsq, *scale, *shift;
    __half *hbuf;
    int *deg, *rowptr, *cursor, *bsum, *bpre;
    int2 *csrp;
    __nv_bfloat16 *B2;
    cudaGetSymbolAddress((void**)&hbuf,   g_h);
    cudaGetSymbolAddress((void**)&aggbuf, g_agg);
    cudaGetSymbolAddress((void**)&B2,     g_B2);
    cudaGetSymbolAddress((void**)&dinv,   g_dinv);
    cudaGetSymbolAddress((void**)&deg,    g_deg);
    cudaGetSymbolAddress((void**)&rowptr, g_rowptr);
    cudaGetSymbolAddress((void**)&cursor, g_cursor);
    cudaGetSymbolAddress((void**)&csrp,   g_csrp);
    cudaGetSymbolAddress((void**)&bsum,   g_bsum);
    cudaGetSymbolAddress((void**)&bpre,   g_bpre);
    cudaGetSymbolAddress((void**)&sum,    g_sum);
    cudaGetSymbolAddress((void**)&sumsq,  g_sumsq);
    cudaGetSymbolAddress((void**)&scale,  g_scale);
    cudaGetSymbolAddress((void**)&shift,  g_shift);

    static int attr_done = 0;
    if (!attr_done) {
        cudaFuncSetAttribute(k_wmma, cudaFuncAttributeMaxDynamicSharedMemorySize, SMEM_WMMA);
        attr_done = 1;
    }

    const int dims[4] = {768, 512, 256, 128};
    const float* gs[3]  = {g1, g2, g3};
    const float* bes[3] = {be1, be2, be3};
    size_t boff[3] = {0, 786432, 1048576};

    // ---- launches 1-3: weight split + degree prep ----
    k_wsplit_all<<<(557056 + 255) / 256, 256>>>(W1, W2, W3, B2);
    k_deg_count<<<(E + 255) / 256, 256>>>(edst, deg, E);
    int nb = (n + 255) / 256;
    k_blocksum_dinv<<<nb, 256>>>(deg, bsum, dinv, n);

    // ---- launch 4: layer-1 GEMM (ncu capture slot) ----
    {
        dim3 ggrid(dims[1] / 128, (n + 127) / 128);
        k_wmma<<<ggrid, 256, SMEM_WMMA>>>(x, B2 + boff[0], hbuf, n, dims[1], dims[0],
                                          scale, shift, 0);
    }

    // ---- remaining graph prep ----
    k_scanb<<<1, 256>>>(bsum, bpre, nb);
    k_rowptr<<<nb, 256>>>(deg, bpre, rowptr, cursor, n);
    k_csr_fill<<<(E + n + 255) / 256, 256>>>(esrc, edst, dinv, cursor, csrp, E, n);

    for (int L = 0; L < 3; L++) {
        int Cin = dims[L], Cout = dims[L + 1];

        if (L > 0) {
            dim3 ggrid(Cout / 128, (n + 127) / 128);
            k_wmma<<<ggrid, 256, SMEM_WMMA>>>(aggbuf, B2 + boff[L], hbuf, n, Cout, Cin,
                                              scale, shift, 1);
        }

        // CSR gather (fp16 h reads, fp32 accumulate)
        int tpr = Cout >> 2;
        int rpb = 256 / tpr;
        k_gather<<<(n + rpb - 1) / rpb, 256>>>(rowptr, csrp, dinv, hbuf, aggbuf, n, Cout);

        // BN statistics (sums pre-zeroed by previous finalize / zero-init)
        int rows_per = (n + 199) / 200;
        dim3 sgrid(Cout / 128, 200);
        k_colstats<<<sgrid, 128>>>(aggbuf, n, Cout, rows_per, sum, sumsq);
        k_finalize<<<1, CMAX>>>(sum, sumsq, gs[L], bes[L], scale, shift, n, Cout);
    }

    // final BN apply (no ReLU) -> d_out
    int n4 = (n * 128) >> 2;
    k_bn_apply<<<(n4 + 255) / 256, 256>>>(aggbuf, scale, shift, (float*)d_out, n, 128);
}